// round 1
// baseline (speedup 1.0000x reference)
#include <cuda_runtime.h>
#include <cuda_bf16.h>

// Problem constants
#define B_  4
#define N_  1024
#define D_  768
#define H_  12
#define DH_ 64
#define BH_ (B_ * H_)      // 48
#define M_  (B_ * N_)      // 4096 rows of x
#define N3_ (3 * D_)       // 2304 output cols of qkv

// Scratch: q,k,v in (B,H,N,Dh) layout + proj (B,H,N)
__device__ float g_q[BH_ * N_ * DH_];
__device__ float g_k[BH_ * N_ * DH_];
__device__ float g_v[BH_ * N_ * DH_];
__device__ float g_proj[BH_ * N_];

// ---------------------------------------------------------------------------
// Kernel 1: qkv = x @ Wqkv^T + bqkv, scattered into per-head q/k/v layout
// C[m, n] = sum_k x[m,k] * W[n,k];  M=4096, N=2304, K=768
// Tile 64x64, K-tile 32, 256 threads, 4x4 microtile, smem stored transposed
// so compute reads are LDS.128 (a: broadcast, b: conflict-free).
// ---------------------------------------------------------------------------
__global__ __launch_bounds__(256) void qkv_gemm_kernel(
    const float* __restrict__ x, const float* __restrict__ W,
    const float* __restrict__ bias)
{
    __shared__ float As[32][64];   // As[k][m_local]
    __shared__ float Bs[32][64];   // Bs[k][n_local]

    const int tid = threadIdx.x;
    const int m0 = blockIdx.y * 64;
    const int n0 = blockIdx.x * 64;
    const int tx = tid & 15;       // 0..15 -> 4 cols each
    const int ty = tid >> 4;       // 0..15 -> 4 rows each

    float acc[4][4];
#pragma unroll
    for (int i = 0; i < 4; ++i)
#pragma unroll
        for (int j = 0; j < 4; ++j) acc[i][j] = 0.f;

    for (int k0 = 0; k0 < D_; k0 += 32) {
#pragma unroll
        for (int it = 0; it < 2; ++it) {
            int idx = it * 256 + tid;          // 0..511
            int r  = idx >> 3;                 // 0..63
            int c4 = (idx & 7) * 4;            // 0,4,..,28
            float4 a = *(const float4*)&x[(size_t)(m0 + r) * D_ + k0 + c4];
            As[c4 + 0][r] = a.x; As[c4 + 1][r] = a.y;
            As[c4 + 2][r] = a.z; As[c4 + 3][r] = a.w;
            float4 b = *(const float4*)&W[(size_t)(n0 + r) * D_ + k0 + c4];
            Bs[c4 + 0][r] = b.x; Bs[c4 + 1][r] = b.y;
            Bs[c4 + 2][r] = b.z; Bs[c4 + 3][r] = b.w;
        }
        __syncthreads();
#pragma unroll
        for (int kk = 0; kk < 32; ++kk) {
            float4 a = *(const float4*)&As[kk][ty * 4];
            float4 b = *(const float4*)&Bs[kk][tx * 4];
            acc[0][0] += a.x * b.x; acc[0][1] += a.x * b.y;
            acc[0][2] += a.x * b.z; acc[0][3] += a.x * b.w;
            acc[1][0] += a.y * b.x; acc[1][1] += a.y * b.y;
            acc[1][2] += a.y * b.z; acc[1][3] += a.y * b.w;
            acc[2][0] += a.z * b.x; acc[2][1] += a.z * b.y;
            acc[2][2] += a.z * b.z; acc[2][3] += a.z * b.w;
            acc[3][0] += a.w * b.x; acc[3][1] += a.w * b.y;
            acc[3][2] += a.w * b.z; acc[3][3] += a.w * b.w;
        }
        __syncthreads();
    }

    // Epilogue: n0 is a multiple of 64 and 768 % 64 == 0, so q/k/v selector and
    // head index are uniform per block.
    const int which = n0 / D_;                  // 0=q, 1=k, 2=v
    const int h     = (n0 % D_) >> 6;           // head
    float* dst = (which == 0) ? g_q : (which == 1) ? g_k : g_v;
    float4 bv = *(const float4*)&bias[n0 + tx * 4];

#pragma unroll
    for (int i = 0; i < 4; ++i) {
        int m  = m0 + ty * 4 + i;
        int bb = m >> 10;           // batch
        int tok = m & 1023;
        float* row = &dst[((size_t)(bb * H_ + h) * N_ + tok) * DH_];
        float4 v;
        v.x = acc[i][0] + bv.x; v.y = acc[i][1] + bv.y;
        v.z = acc[i][2] + bv.z; v.w = acc[i][3] + bv.w;
        *(float4*)&row[tx * 4] = v;
    }
}

// ---------------------------------------------------------------------------
// Kernel 2: proj[b,h,n] = sum_c coords[b,n,c] * rel_weight[h,c]
// ---------------------------------------------------------------------------
__global__ void proj_kernel(const float* __restrict__ coords,
                            const float* __restrict__ relw)
{
    int idx = blockIdx.x * blockDim.x + threadIdx.x;   // 0..BH_*N_-1
    if (idx >= BH_ * N_) return;
    int n = idx & 1023;
    int h = (idx >> 10) % H_;
    int b = idx / (H_ * N_);
    const float* c = &coords[(size_t)(b * N_ + n) * 3];
    const float* w = &relw[h * 3];
    g_proj[idx] = c[0] * w[0] + c[1] * w[1] + c[2] * w[2];
}

// ---------------------------------------------------------------------------
// Kernel 3: flash attention with rank-1 coord bias.
// grid = (N/128, B*H), 128 threads; each thread owns one query row.
// Key/value processed in tiles of 32 through shared memory; per-tile scores
// cached in registers so the online-softmax correction is applied once per
// tile (2 FMA/key amortized) instead of per key.
// ---------------------------------------------------------------------------
__global__ __launch_bounds__(128) void attn_kernel(float* __restrict__ out)
{
    __shared__ float Ks[32][64];
    __shared__ float Vs[32][64];
    __shared__ float Ps[32];

    const int bh = blockIdx.y;                        // 0..47
    const int i  = blockIdx.x * 128 + threadIdx.x;    // query index
    const float scale = 0.125f;                       // 1/sqrt(64)

    float q[64];
    {
        const float* qp = &g_q[((size_t)bh * N_ + i) * DH_];
#pragma unroll
        for (int d = 0; d < 64; d += 4) {
            float4 v = *(const float4*)&qp[d];
            q[d] = v.x; q[d + 1] = v.y; q[d + 2] = v.z; q[d + 3] = v.w;
        }
    }
    const float proj_i = g_proj[bh * N_ + i];

    float m = -1e30f, l = 0.f;
    float o[64];
#pragma unroll
    for (int d = 0; d < 64; ++d) o[d] = 0.f;

    for (int kt = 0; kt < N_ / 32; ++kt) {
        __syncthreads();
        {
            const size_t base = ((size_t)bh * N_ + kt * 32) * DH_;
#pragma unroll
            for (int t = 0; t < 4; ++t) {
                int idx = t * 128 + threadIdx.x;   // 0..511
                int r = idx >> 4;
                int c = (idx & 15) * 4;
                *(float4*)&Ks[r][c] = *(const float4*)&g_k[base + r * 64 + c];
                *(float4*)&Vs[r][c] = *(const float4*)&g_v[base + r * 64 + c];
            }
            if (threadIdx.x < 32)
                Ps[threadIdx.x] = g_proj[bh * N_ + kt * 32 + threadIdx.x];
        }
        __syncthreads();

        float s[32];
        float tmax = -1e30f;
#pragma unroll
        for (int j = 0; j < 32; ++j) {
            float acc = 0.f;
#pragma unroll
            for (int d = 0; d < 64; d += 4) {
                float4 kv = *(const float4*)&Ks[j][d];
                acc += q[d] * kv.x + q[d + 1] * kv.y
                     + q[d + 2] * kv.z + q[d + 3] * kv.w;
            }
            float sv = acc * scale + proj_i - Ps[j];
            s[j] = sv;
            tmax = fmaxf(tmax, sv);
        }

        float mnew = fmaxf(m, tmax);
        float corr = __expf(m - mnew);
        l *= corr;
#pragma unroll
        for (int d = 0; d < 64; ++d) o[d] *= corr;

#pragma unroll
        for (int j = 0; j < 32; ++j) {
            float p = __expf(s[j] - mnew);
            l += p;
#pragma unroll
            for (int d = 0; d < 64; d += 4) {
                float4 vv = *(const float4*)&Vs[j][d];
                o[d]     += p * vv.x;
                o[d + 1] += p * vv.y;
                o[d + 2] += p * vv.z;
                o[d + 3] += p * vv.w;
            }
        }
        m = mnew;
    }

    const float inv = 1.f / l;
    const int b = bh / H_;
    const int h = bh % H_;
    float* op = &out[((size_t)(b * N_ + i)) * D_ + h * DH_];
#pragma unroll
    for (int d = 0; d < 64; d += 4) {
        float4 v;
        v.x = o[d] * inv; v.y = o[d + 1] * inv;
        v.z = o[d + 2] * inv; v.w = o[d + 3] * inv;
        *(float4*)&op[d] = v;
    }
}

// ---------------------------------------------------------------------------
extern "C" void kernel_launch(void* const* d_in, const int* in_sizes, int n_in,
                              void* d_out, int out_size)
{
    const float* x     = (const float*)d_in[0];
    const float* coords= (const float*)d_in[1];
    const float* Wqkv  = (const float*)d_in[2];
    const float* bqkv  = (const float*)d_in[3];
    const float* relw  = (const float*)d_in[4];
    float* out = (float*)d_out;

    (void)in_sizes; (void)n_in; (void)out_size;

    // 1. coord projection (rank-1 bias)
    proj_kernel<<<(BH_ * N_ + 255) / 256, 256>>>(coords, relw);

    // 2. QKV GEMM + bias + head split
    dim3 ggrid(N3_ / 64, M_ / 64);   // (36, 64)
    qkv_gemm_kernel<<<ggrid, 256>>>(x, Wqkv, bqkv);

    // 3. flash attention + output merge
    dim3 agrid(N_ / 128, BH_);       // (8, 48)
    attn_kernel<<<agrid, 128>>>(out);
}

// round 2
// speedup vs baseline: 1.5843x; 1.5843x over previous
#include <cuda_runtime.h>
#include <cuda_bf16.h>
#include <cstdint>

// Problem constants
#define B_  4
#define N_  1024
#define D_  768
#define H_  12
#define DH_ 64
#define BH_ (B_ * H_)      // 48
#define M_  (B_ * N_)      // 4096 rows of x
#define N3_ (3 * D_)       // 2304 output cols of qkv

// Scratch: q,k,v in (B,H,N,Dh) layout + proj (B,H,N)
__device__ float g_q[BH_ * N_ * DH_];
__device__ float g_k[BH_ * N_ * DH_];
__device__ float g_v[BH_ * N_ * DH_];
__device__ float g_proj[BH_ * N_];

// ---------------------------------------------------------------------------
// Kernel 1: qkv = x @ Wqkv^T + bqkv, scattered into per-head q/k/v layout
// ---------------------------------------------------------------------------
__global__ __launch_bounds__(256) void qkv_gemm_kernel(
    const float* __restrict__ x, const float* __restrict__ W,
    const float* __restrict__ bias)
{
    __shared__ float As[32][64];   // As[k][m_local]
    __shared__ float Bs[32][64];   // Bs[k][n_local]

    const int tid = threadIdx.x;
    const int m0 = blockIdx.y * 64;
    const int n0 = blockIdx.x * 64;
    const int tx = tid & 15;
    const int ty = tid >> 4;

    float acc[4][4];
#pragma unroll
    for (int i = 0; i < 4; ++i)
#pragma unroll
        for (int j = 0; j < 4; ++j) acc[i][j] = 0.f;

    for (int k0 = 0; k0 < D_; k0 += 32) {
#pragma unroll
        for (int it = 0; it < 2; ++it) {
            int idx = it * 256 + tid;
            int r  = idx >> 3;
            int c4 = (idx & 7) * 4;
            float4 a = *(const float4*)&x[(size_t)(m0 + r) * D_ + k0 + c4];
            As[c4 + 0][r] = a.x; As[c4 + 1][r] = a.y;
            As[c4 + 2][r] = a.z; As[c4 + 3][r] = a.w;
            float4 b = *(const float4*)&W[(size_t)(n0 + r) * D_ + k0 + c4];
            Bs[c4 + 0][r] = b.x; Bs[c4 + 1][r] = b.y;
            Bs[c4 + 2][r] = b.z; Bs[c4 + 3][r] = b.w;
        }
        __syncthreads();
#pragma unroll
        for (int kk = 0; kk < 32; ++kk) {
            float4 a = *(const float4*)&As[kk][ty * 4];
            float4 b = *(const float4*)&Bs[kk][tx * 4];
            acc[0][0] += a.x * b.x; acc[0][1] += a.x * b.y;
            acc[0][2] += a.x * b.z; acc[0][3] += a.x * b.w;
            acc[1][0] += a.y * b.x; acc[1][1] += a.y * b.y;
            acc[1][2] += a.y * b.z; acc[1][3] += a.y * b.w;
            acc[2][0] += a.z * b.x; acc[2][1] += a.z * b.y;
            acc[2][2] += a.z * b.z; acc[2][3] += a.z * b.w;
            acc[3][0] += a.w * b.x; acc[3][1] += a.w * b.y;
            acc[3][2] += a.w * b.z; acc[3][3] += a.w * b.w;
        }
        __syncthreads();
    }

    const int which = n0 / D_;
    const int h     = (n0 % D_) >> 6;
    float* dst = (which == 0) ? g_q : (which == 1) ? g_k : g_v;
    float4 bv = *(const float4*)&bias[n0 + tx * 4];

#pragma unroll
    for (int i = 0; i < 4; ++i) {
        int m  = m0 + ty * 4 + i;
        int bb = m >> 10;
        int tok = m & 1023;
        float* row = &dst[((size_t)(bb * H_ + h) * N_ + tok) * DH_];
        float4 v;
        v.x = acc[i][0] + bv.x; v.y = acc[i][1] + bv.y;
        v.z = acc[i][2] + bv.z; v.w = acc[i][3] + bv.w;
        *(float4*)&row[tx * 4] = v;
    }
}

// ---------------------------------------------------------------------------
// Kernel 2: proj[b,h,n] = sum_c coords[b,n,c] * rel_weight[h,c]
// ---------------------------------------------------------------------------
__global__ void proj_kernel(const float* __restrict__ coords,
                            const float* __restrict__ relw)
{
    int idx = blockIdx.x * blockDim.x + threadIdx.x;
    if (idx >= BH_ * N_) return;
    int n = idx & 1023;
    int h = (idx >> 10) % H_;
    int b = idx / (H_ * N_);
    const float* c = &coords[(size_t)(b * N_ + n) * 3];
    const float* w = &relw[h * 3];
    g_proj[idx] = c[0] * w[0] + c[1] * w[1] + c[2] * w[2];
}

// ---------------------------------------------------------------------------
// Kernel 3: tensor-core flash attention (tf32 mma.sync.m16n8k8).
// Block: 64 queries x one (b,h); 4 warps, each owns 16 query rows.
// QK^T uses 3xTF32 split (fp32-accurate scores); PV uses single tf32.
// Key/value tiles of 64 in dynamic smem; padded strides for conflict-free LDS.
// ---------------------------------------------------------------------------
#define QSTR 68   // stride for sQ/sP and sK (68 % 32 == 4 -> conflict-free frag loads)
#define VSTR 72   // stride for sV (72 % 32 == 8 -> conflict-free B-frag loads)
#define ATTN_SMEM ((3 * 64 * QSTR + 64 * VSTR + 64) * 4)

__device__ __forceinline__ uint32_t f2tf32(float x) {
    uint32_t r;
    asm("cvt.rna.tf32.f32 %0, %1;" : "=r"(r) : "f"(x));
    return r;
}

__device__ __forceinline__ void mma8(float c[4], const uint32_t a[4],
                                     const uint32_t b[2]) {
    asm volatile(
        "mma.sync.aligned.m16n8k8.row.col.f32.tf32.tf32.f32 "
        "{%0,%1,%2,%3}, {%4,%5,%6,%7}, {%8,%9}, {%0,%1,%2,%3};"
        : "+f"(c[0]), "+f"(c[1]), "+f"(c[2]), "+f"(c[3])
        : "r"(a[0]), "r"(a[1]), "r"(a[2]), "r"(a[3]), "r"(b[0]), "r"(b[1]));
}

__global__ __launch_bounds__(128) void attn_mma_kernel(float* __restrict__ out)
{
    extern __shared__ float sm[];
    float* sQ  = sm;                      // 64 x QSTR (reused as P after Q consumed)
    float* sKh = sQ  + 64 * QSTR;         // 64 x QSTR (tf32 hi)
    float* sKl = sKh + 64 * QSTR;         // 64 x QSTR (tf32 lo)
    float* sV  = sKl + 64 * QSTR;         // 64 x VSTR
    float* sPj = sV  + 64 * VSTR;         // 64 proj of keys

    const int bh = blockIdx.y;
    const int q0 = blockIdx.x * 64;
    const int tid = threadIdx.x;
    const int w = tid >> 5;
    const int lane = tid & 31;
    const int g = lane >> 2;      // 0..7
    const int tg = lane & 3;      // 0..3
    const int r0 = w * 16 + g;    // this thread's block-local rows
    const int r1 = r0 + 8;

    // ---- load Q tile, build A fragments (hi/lo tf32) in registers ----
#pragma unroll
    for (int t = 0; t < 8; ++t) {
        int idx = t * 128 + tid;
        int r = idx >> 4;
        int c4 = (idx & 15) << 2;
        *(float4*)&sQ[r * QSTR + c4] =
            *(const float4*)&g_q[((size_t)bh * N_ + q0 + r) * DH_ + c4];
    }
    __syncthreads();

    uint32_t qhi[8][4], qlo[8][4];
#pragma unroll
    for (int kc = 0; kc < 8; ++kc) {
        float f0 = sQ[r0 * QSTR + kc * 8 + tg];
        float f1 = sQ[r1 * QSTR + kc * 8 + tg];
        float f2 = sQ[r0 * QSTR + kc * 8 + tg + 4];
        float f3 = sQ[r1 * QSTR + kc * 8 + tg + 4];
        qhi[kc][0] = f2tf32(f0); qlo[kc][0] = f2tf32(f0 - __uint_as_float(qhi[kc][0]));
        qhi[kc][1] = f2tf32(f1); qlo[kc][1] = f2tf32(f1 - __uint_as_float(qhi[kc][1]));
        qhi[kc][2] = f2tf32(f2); qlo[kc][2] = f2tf32(f2 - __uint_as_float(qhi[kc][2]));
        qhi[kc][3] = f2tf32(f3); qlo[kc][3] = f2tf32(f3 - __uint_as_float(qhi[kc][3]));
    }
    __syncthreads();    // sQ may now be reused as sP

    const float pi0 = g_proj[bh * N_ + q0 + r0];
    const float pi1 = g_proj[bh * N_ + q0 + r1];

    float o[8][4];
#pragma unroll
    for (int nt = 0; nt < 8; ++nt)
#pragma unroll
        for (int j = 0; j < 4; ++j) o[nt][j] = 0.f;
    float m0 = -1e30f, m1 = -1e30f, l0 = 0.f, l1 = 0.f;

    for (int kt = 0; kt < N_ / 64; ++kt) {
        // ---- cooperative load of K (hi/lo tf32) and V tiles ----
        const size_t kbase = ((size_t)bh * N_ + kt * 64) * DH_;
#pragma unroll
        for (int t = 0; t < 8; ++t) {
            int idx = t * 128 + tid;
            int r = idx >> 4;
            int c4 = (idx & 15) << 2;
            float4 kf = *(const float4*)&g_k[kbase + r * DH_ + c4];
            uint32_t h0 = f2tf32(kf.x), h1 = f2tf32(kf.y),
                     h2 = f2tf32(kf.z), h3 = f2tf32(kf.w);
            float4 hv = make_float4(__uint_as_float(h0), __uint_as_float(h1),
                                    __uint_as_float(h2), __uint_as_float(h3));
            float4 lv = make_float4(
                __uint_as_float(f2tf32(kf.x - hv.x)),
                __uint_as_float(f2tf32(kf.y - hv.y)),
                __uint_as_float(f2tf32(kf.z - hv.z)),
                __uint_as_float(f2tf32(kf.w - hv.w)));
            *(float4*)&sKh[r * QSTR + c4] = hv;
            *(float4*)&sKl[r * QSTR + c4] = lv;
            *(float4*)&sV[r * VSTR + c4] =
                *(const float4*)&g_v[kbase + r * DH_ + c4];
        }
        if (tid < 64) sPj[tid] = g_proj[bh * N_ + kt * 64 + tid];
        __syncthreads();

        // ---- S = Q K^T via 3xTF32 split ----
        float s[8][4];
#pragma unroll
        for (int nt = 0; nt < 8; ++nt) {
            float c[4] = {0.f, 0.f, 0.f, 0.f};
            const int key = nt * 8 + g;
#pragma unroll
            for (int kc = 0; kc < 8; ++kc) {
                uint32_t bhf[2], blf[2];
                bhf[0] = __float_as_uint(sKh[key * QSTR + kc * 8 + tg]);
                bhf[1] = __float_as_uint(sKh[key * QSTR + kc * 8 + tg + 4]);
                blf[0] = __float_as_uint(sKl[key * QSTR + kc * 8 + tg]);
                blf[1] = __float_as_uint(sKl[key * QSTR + kc * 8 + tg + 4]);
                mma8(c, qhi[kc], bhf);
                mma8(c, qhi[kc], blf);
                mma8(c, qlo[kc], bhf);
            }
            float pj0 = sPj[nt * 8 + 2 * tg];
            float pj1 = sPj[nt * 8 + 2 * tg + 1];
            s[nt][0] = c[0] * 0.125f + pi0 - pj0;
            s[nt][1] = c[1] * 0.125f + pi0 - pj1;
            s[nt][2] = c[2] * 0.125f + pi1 - pj0;
            s[nt][3] = c[3] * 0.125f + pi1 - pj1;
        }

        // ---- online softmax ----
        float t0 = -1e30f, t1 = -1e30f;
#pragma unroll
        for (int nt = 0; nt < 8; ++nt) {
            t0 = fmaxf(t0, fmaxf(s[nt][0], s[nt][1]));
            t1 = fmaxf(t1, fmaxf(s[nt][2], s[nt][3]));
        }
        t0 = fmaxf(t0, __shfl_xor_sync(0xffffffffu, t0, 1));
        t0 = fmaxf(t0, __shfl_xor_sync(0xffffffffu, t0, 2));
        t1 = fmaxf(t1, __shfl_xor_sync(0xffffffffu, t1, 1));
        t1 = fmaxf(t1, __shfl_xor_sync(0xffffffffu, t1, 2));

        float mn0 = fmaxf(m0, t0), mn1 = fmaxf(m1, t1);
        float cor0 = __expf(m0 - mn0), cor1 = __expf(m1 - mn1);
        l0 *= cor0; l1 *= cor1;
#pragma unroll
        for (int nt = 0; nt < 8; ++nt) {
            o[nt][0] *= cor0; o[nt][1] *= cor0;
            o[nt][2] *= cor1; o[nt][3] *= cor1;
        }

        float ls0 = 0.f, ls1 = 0.f;
#pragma unroll
        for (int nt = 0; nt < 8; ++nt) {
            float p00 = __expf(s[nt][0] - mn0);
            float p01 = __expf(s[nt][1] - mn0);
            float p10 = __expf(s[nt][2] - mn1);
            float p11 = __expf(s[nt][3] - mn1);
            ls0 += p00 + p01; ls1 += p10 + p11;
            *(float2*)&sQ[r0 * QSTR + nt * 8 + 2 * tg] = make_float2(p00, p01);
            *(float2*)&sQ[r1 * QSTR + nt * 8 + 2 * tg] = make_float2(p10, p11);
        }
        ls0 += __shfl_xor_sync(0xffffffffu, ls0, 1);
        ls0 += __shfl_xor_sync(0xffffffffu, ls0, 2);
        ls1 += __shfl_xor_sync(0xffffffffu, ls1, 1);
        ls1 += __shfl_xor_sync(0xffffffffu, ls1, 2);
        l0 += ls0; l1 += ls1;
        m0 = mn0; m1 = mn1;
        __syncwarp();     // P visible within the owning warp

        // ---- O += P V  (single tf32; HW truncation of fp32 operands) ----
#pragma unroll
        for (int kc = 0; kc < 8; ++kc) {
            uint32_t a[4];
            a[0] = __float_as_uint(sQ[r0 * QSTR + kc * 8 + tg]);
            a[1] = __float_as_uint(sQ[r1 * QSTR + kc * 8 + tg]);
            a[2] = __float_as_uint(sQ[r0 * QSTR + kc * 8 + tg + 4]);
            a[3] = __float_as_uint(sQ[r1 * QSTR + kc * 8 + tg + 4]);
#pragma unroll
            for (int nt = 0; nt < 8; ++nt) {
                uint32_t b[2];
                b[0] = __float_as_uint(sV[(kc * 8 + tg) * VSTR + nt * 8 + g]);
                b[1] = __float_as_uint(sV[(kc * 8 + tg + 4) * VSTR + nt * 8 + g]);
                mma8(o[nt], a, b);
            }
        }
        __syncthreads();   // before next tile overwrites K/V
    }

    // ---- epilogue ----
    const float inv0 = 1.f / l0, inv1 = 1.f / l1;
    const int b = bh / H_;
    const int h = bh % H_;
    const int qA = q0 + r0, qB = q0 + r1;
    float* oA = &out[((size_t)(b * N_ + qA)) * D_ + h * DH_];
    float* oB = &out[((size_t)(b * N_ + qB)) * D_ + h * DH_];
#pragma unroll
    for (int nt = 0; nt < 8; ++nt) {
        *(float2*)&oA[nt * 8 + 2 * tg] = make_float2(o[nt][0] * inv0, o[nt][1] * inv0);
        *(float2*)&oB[nt * 8 + 2 * tg] = make_float2(o[nt][2] * inv1, o[nt][3] * inv1);
    }
}

// ---------------------------------------------------------------------------
extern "C" void kernel_launch(void* const* d_in, const int* in_sizes, int n_in,
                              void* d_out, int out_size)
{
    const float* x     = (const float*)d_in[0];
    const float* coords= (const float*)d_in[1];
    const float* Wqkv  = (const float*)d_in[2];
    const float* bqkv  = (const float*)d_in[3];
    const float* relw  = (const float*)d_in[4];
    float* out = (float*)d_out;

    (void)in_sizes; (void)n_in; (void)out_size;

    static bool attr_set = false;
    if (!attr_set) {
        cudaFuncSetAttribute(attn_mma_kernel,
                             cudaFuncAttributeMaxDynamicSharedMemorySize,
                             ATTN_SMEM);
        attr_set = true;
    }

    proj_kernel<<<(BH_ * N_ + 255) / 256, 256>>>(coords, relw);

    dim3 ggrid(N3_ / 64, M_ / 64);
    qkv_gemm_kernel<<<ggrid, 256>>>(x, Wqkv, bqkv);

    dim3 agrid(N_ / 64, BH_);        // (16, 48)
    attn_mma_kernel<<<agrid, 128, ATTN_SMEM>>>(out);
}

// round 3
// speedup vs baseline: 3.4171x; 2.1569x over previous
#include <cuda_runtime.h>
#include <cuda_bf16.h>
#include <cstdint>

// Problem constants
#define B_  4
#define N_  1024
#define D_  768
#define H_  12
#define DH_ 64
#define BH_ (B_ * H_)      // 48
#define M_  (B_ * N_)      // 4096 rows of x
#define N3_ (3 * D_)       // 2304 output cols of qkv

// Scratch: q,k,v in (B,H,N,Dh) layout + proj (B,H,N)
__device__ float g_q[BH_ * N_ * DH_];
__device__ float g_k[BH_ * N_ * DH_];
__device__ float g_v[BH_ * N_ * DH_];
__device__ float g_proj[BH_ * N_];

// ---------------------------------------------------------------------------
// bf16 m16n8k16 mma (row.col, fp32 accumulate)
// ---------------------------------------------------------------------------
__device__ __forceinline__ void mma16816(float c[4], const uint32_t a[4],
                                         const uint32_t b[2]) {
    asm volatile(
        "mma.sync.aligned.m16n8k16.row.col.f32.bf16.bf16.f32 "
        "{%0,%1,%2,%3}, {%4,%5,%6,%7}, {%8,%9}, {%0,%1,%2,%3};"
        : "+f"(c[0]), "+f"(c[1]), "+f"(c[2]), "+f"(c[3])
        : "r"(a[0]), "r"(a[1]), "r"(a[2]), "r"(a[3]), "r"(b[0]), "r"(b[1]));
}

// ---------------------------------------------------------------------------
// Kernel 1: qkv = x @ Wqkv^T + bqkv via bf16 tensor cores (3-term hi/lo split),
// scattered into per-head q/k/v layout.
// Block 128x128, K-tile 32, 256 threads = 8 warps (2M x 4N), warp = 64x32.
// Smem stride 40 halves -> conflict-free fragment LDS.
// ---------------------------------------------------------------------------
#define ASTR 40

__global__ __launch_bounds__(256) void qkv_gemm_bf16_kernel(
    const float* __restrict__ x, const float* __restrict__ W,
    const float* __restrict__ bias)
{
    __shared__ __nv_bfloat16 Ah[128][ASTR];
    __shared__ __nv_bfloat16 Al[128][ASTR];
    __shared__ __nv_bfloat16 Bh[128][ASTR];
    __shared__ __nv_bfloat16 Bl[128][ASTR];

    const int tid  = threadIdx.x;
    const int warp = tid >> 5;
    const int lane = tid & 31;
    const int wm = warp >> 2;          // 0..1  (M direction)
    const int wn = warp & 3;           // 0..3  (N direction)
    const int g  = lane >> 2;          // 0..7
    const int tg = lane & 3;           // 0..3
    const int m0 = blockIdx.y * 128;
    const int n0 = blockIdx.x * 128;

    float acc[4][4][4];
#pragma unroll
    for (int mt = 0; mt < 4; ++mt)
#pragma unroll
        for (int nt = 0; nt < 4; ++nt)
#pragma unroll
            for (int j = 0; j < 4; ++j) acc[mt][nt][j] = 0.f;

    for (int k0 = 0; k0 < D_; k0 += 32) {
        // ---- load 128x32 of A and B, convert to bf16 hi/lo ----
#pragma unroll
        for (int it = 0; it < 4; ++it) {
            int idx = it * 256 + tid;          // 0..1023
            int r   = idx >> 3;                // 0..127
            int c4  = (idx & 7) * 4;           // 0..28
            float4 a = *(const float4*)&x[(size_t)(m0 + r) * D_ + k0 + c4];
            __nv_bfloat16 h0 = __float2bfloat16(a.x);
            __nv_bfloat16 h1 = __float2bfloat16(a.y);
            __nv_bfloat16 h2 = __float2bfloat16(a.z);
            __nv_bfloat16 h3 = __float2bfloat16(a.w);
            Ah[r][c4 + 0] = h0; Ah[r][c4 + 1] = h1;
            Ah[r][c4 + 2] = h2; Ah[r][c4 + 3] = h3;
            Al[r][c4 + 0] = __float2bfloat16(a.x - __bfloat162float(h0));
            Al[r][c4 + 1] = __float2bfloat16(a.y - __bfloat162float(h1));
            Al[r][c4 + 2] = __float2bfloat16(a.z - __bfloat162float(h2));
            Al[r][c4 + 3] = __float2bfloat16(a.w - __bfloat162float(h3));

            float4 b = *(const float4*)&W[(size_t)(n0 + r) * D_ + k0 + c4];
            __nv_bfloat16 p0 = __float2bfloat16(b.x);
            __nv_bfloat16 p1 = __float2bfloat16(b.y);
            __nv_bfloat16 p2 = __float2bfloat16(b.z);
            __nv_bfloat16 p3 = __float2bfloat16(b.w);
            Bh[r][c4 + 0] = p0; Bh[r][c4 + 1] = p1;
            Bh[r][c4 + 2] = p2; Bh[r][c4 + 3] = p3;
            Bl[r][c4 + 0] = __float2bfloat16(b.x - __bfloat162float(p0));
            Bl[r][c4 + 1] = __float2bfloat16(b.y - __bfloat162float(p1));
            Bl[r][c4 + 2] = __float2bfloat16(b.z - __bfloat162float(p2));
            Bl[r][c4 + 3] = __float2bfloat16(b.w - __bfloat162float(p3));
        }
        __syncthreads();

#pragma unroll
        for (int ks = 0; ks < 2; ++ks) {
            const int kb = ks * 16 + 2 * tg;
            uint32_t ahi[4][4], alo[4][4];
#pragma unroll
            for (int mt = 0; mt < 4; ++mt) {
                int r0 = wm * 64 + mt * 16 + g;
                int r1 = r0 + 8;
                ahi[mt][0] = *(const uint32_t*)&Ah[r0][kb];
                ahi[mt][1] = *(const uint32_t*)&Ah[r1][kb];
                ahi[mt][2] = *(const uint32_t*)&Ah[r0][kb + 8];
                ahi[mt][3] = *(const uint32_t*)&Ah[r1][kb + 8];
                alo[mt][0] = *(const uint32_t*)&Al[r0][kb];
                alo[mt][1] = *(const uint32_t*)&Al[r1][kb];
                alo[mt][2] = *(const uint32_t*)&Al[r0][kb + 8];
                alo[mt][3] = *(const uint32_t*)&Al[r1][kb + 8];
            }
            uint32_t bhi[4][2], blo[4][2];
#pragma unroll
            for (int nt = 0; nt < 4; ++nt) {
                int n = wn * 32 + nt * 8 + g;
                bhi[nt][0] = *(const uint32_t*)&Bh[n][kb];
                bhi[nt][1] = *(const uint32_t*)&Bh[n][kb + 8];
                blo[nt][0] = *(const uint32_t*)&Bl[n][kb];
                blo[nt][1] = *(const uint32_t*)&Bl[n][kb + 8];
            }
#pragma unroll
            for (int mt = 0; mt < 4; ++mt)
#pragma unroll
                for (int nt = 0; nt < 4; ++nt) {
                    mma16816(acc[mt][nt], ahi[mt], bhi[nt]);
                    mma16816(acc[mt][nt], ahi[mt], blo[nt]);
                    mma16816(acc[mt][nt], alo[mt], bhi[nt]);
                }
        }
        __syncthreads();
    }

    // ---- epilogue: bias add + scatter to q/k/v (B,H,N,Dh) ----
    const int which = n0 / D_;                 // block fully inside q, k, or v
    float* dst = (which == 0) ? g_q : (which == 1) ? g_k : g_v;
    const int colbase = n0 % D_;

#pragma unroll
    for (int nt = 0; nt < 4; ++nt) {
        const int cloc = wn * 32 + nt * 8 + 2 * tg;
        const int col  = colbase + cloc;       // 0..767 inside section
        const int h    = col >> 6;
        const int d    = col & 63;
        float2 bv = *(const float2*)&bias[n0 + cloc];
#pragma unroll
        for (int mt = 0; mt < 4; ++mt) {
            int rA = m0 + wm * 64 + mt * 16 + g;
            int rB = rA + 8;
            int bb = rA >> 10;                 // batch (same for rA, rB)
            float* rowA = &dst[((size_t)(bb * H_ + h) * N_ + (rA & 1023)) * DH_ + d];
            float* rowB = &dst[((size_t)(bb * H_ + h) * N_ + (rB & 1023)) * DH_ + d];
            *(float2*)rowA = make_float2(acc[mt][nt][0] + bv.x,
                                         acc[mt][nt][1] + bv.y);
            *(float2*)rowB = make_float2(acc[mt][nt][2] + bv.x,
                                         acc[mt][nt][3] + bv.y);
        }
    }
}

// ---------------------------------------------------------------------------
// Kernel 2: proj[b,h,n] = sum_c coords[b,n,c] * rel_weight[h,c]
// ---------------------------------------------------------------------------
__global__ void proj_kernel(const float* __restrict__ coords,
                            const float* __restrict__ relw)
{
    int idx = blockIdx.x * blockDim.x + threadIdx.x;
    if (idx >= BH_ * N_) return;
    int n = idx & 1023;
    int h = (idx >> 10) % H_;
    int b = idx / (H_ * N_);
    const float* c = &coords[(size_t)(b * N_ + n) * 3];
    const float* w = &relw[h * 3];
    g_proj[idx] = c[0] * w[0] + c[1] * w[1] + c[2] * w[2];
}

// ---------------------------------------------------------------------------
// Kernel 3: tensor-core flash attention (tf32 mma.sync.m16n8k8).
// ---------------------------------------------------------------------------
#define QSTR 68
#define VSTR 72
#define ATTN_SMEM ((3 * 64 * QSTR + 64 * VSTR + 64) * 4)

__device__ __forceinline__ uint32_t f2tf32(float x) {
    uint32_t r;
    asm("cvt.rna.tf32.f32 %0, %1;" : "=r"(r) : "f"(x));
    return r;
}

__device__ __forceinline__ void mma8(float c[4], const uint32_t a[4],
                                     const uint32_t b[2]) {
    asm volatile(
        "mma.sync.aligned.m16n8k8.row.col.f32.tf32.tf32.f32 "
        "{%0,%1,%2,%3}, {%4,%5,%6,%7}, {%8,%9}, {%0,%1,%2,%3};"
        : "+f"(c[0]), "+f"(c[1]), "+f"(c[2]), "+f"(c[3])
        : "r"(a[0]), "r"(a[1]), "r"(a[2]), "r"(a[3]), "r"(b[0]), "r"(b[1]));
}

__global__ __launch_bounds__(128) void attn_mma_kernel(float* __restrict__ out)
{
    extern __shared__ float sm[];
    float* sQ  = sm;                      // 64 x QSTR (reused as P after Q consumed)
    float* sKh = sQ  + 64 * QSTR;         // 64 x QSTR (tf32 hi)
    float* sKl = sKh + 64 * QSTR;         // 64 x QSTR (tf32 lo)
    float* sV  = sKl + 64 * QSTR;         // 64 x VSTR
    float* sPj = sV  + 64 * VSTR;         // 64 proj of keys

    const int bh = blockIdx.y;
    const int q0 = blockIdx.x * 64;
    const int tid = threadIdx.x;
    const int w = tid >> 5;
    const int lane = tid & 31;
    const int g = lane >> 2;
    const int tg = lane & 3;
    const int r0 = w * 16 + g;
    const int r1 = r0 + 8;

#pragma unroll
    for (int t = 0; t < 8; ++t) {
        int idx = t * 128 + tid;
        int r = idx >> 4;
        int c4 = (idx & 15) << 2;
        *(float4*)&sQ[r * QSTR + c4] =
            *(const float4*)&g_q[((size_t)bh * N_ + q0 + r) * DH_ + c4];
    }
    __syncthreads();

    uint32_t qhi[8][4], qlo[8][4];
#pragma unroll
    for (int kc = 0; kc < 8; ++kc) {
        float f0 = sQ[r0 * QSTR + kc * 8 + tg];
        float f1 = sQ[r1 * QSTR + kc * 8 + tg];
        float f2 = sQ[r0 * QSTR + kc * 8 + tg + 4];
        float f3 = sQ[r1 * QSTR + kc * 8 + tg + 4];
        qhi[kc][0] = f2tf32(f0); qlo[kc][0] = f2tf32(f0 - __uint_as_float(qhi[kc][0]));
        qhi[kc][1] = f2tf32(f1); qlo[kc][1] = f2tf32(f1 - __uint_as_float(qhi[kc][1]));
        qhi[kc][2] = f2tf32(f2); qlo[kc][2] = f2tf32(f2 - __uint_as_float(qhi[kc][2]));
        qhi[kc][3] = f2tf32(f3); qlo[kc][3] = f2tf32(f3 - __uint_as_float(qhi[kc][3]));
    }
    __syncthreads();

    const float pi0 = g_proj[bh * N_ + q0 + r0];
    const float pi1 = g_proj[bh * N_ + q0 + r1];

    float o[8][4];
#pragma unroll
    for (int nt = 0; nt < 8; ++nt)
#pragma unroll
        for (int j = 0; j < 4; ++j) o[nt][j] = 0.f;
    float m0 = -1e30f, m1 = -1e30f, l0 = 0.f, l1 = 0.f;

    for (int kt = 0; kt < N_ / 64; ++kt) {
        const size_t kbase = ((size_t)bh * N_ + kt * 64) * DH_;
#pragma unroll
        for (int t = 0; t < 8; ++t) {
            int idx = t * 128 + tid;
            int r = idx >> 4;
            int c4 = (idx & 15) << 2;
            float4 kf = *(const float4*)&g_k[kbase + r * DH_ + c4];
            uint32_t h0 = f2tf32(kf.x), h1 = f2tf32(kf.y),
                     h2 = f2tf32(kf.z), h3 = f2tf32(kf.w);
            float4 hv = make_float4(__uint_as_float(h0), __uint_as_float(h1),
                                    __uint_as_float(h2), __uint_as_float(h3));
            float4 lv = make_float4(
                __uint_as_float(f2tf32(kf.x - hv.x)),
                __uint_as_float(f2tf32(kf.y - hv.y)),
                __uint_as_float(f2tf32(kf.z - hv.z)),
                __uint_as_float(f2tf32(kf.w - hv.w)));
            *(float4*)&sKh[r * QSTR + c4] = hv;
            *(float4*)&sKl[r * QSTR + c4] = lv;
            *(float4*)&sV[r * VSTR + c4] =
                *(const float4*)&g_v[kbase + r * DH_ + c4];
        }
        if (tid < 64) sPj[tid] = g_proj[bh * N_ + kt * 64 + tid];
        __syncthreads();

        float s[8][4];
#pragma unroll
        for (int nt = 0; nt < 8; ++nt) {
            float c[4] = {0.f, 0.f, 0.f, 0.f};
            const int key = nt * 8 + g;
#pragma unroll
            for (int kc = 0; kc < 8; ++kc) {
                uint32_t bhf[2], blf[2];
                bhf[0] = __float_as_uint(sKh[key * QSTR + kc * 8 + tg]);
                bhf[1] = __float_as_uint(sKh[key * QSTR + kc * 8 + tg + 4]);
                blf[0] = __float_as_uint(sKl[key * QSTR + kc * 8 + tg]);
                blf[1] = __float_as_uint(sKl[key * QSTR + kc * 8 + tg + 4]);
                mma8(c, qhi[kc], bhf);
                mma8(c, qhi[kc], blf);
                mma8(c, qlo[kc], bhf);
            }
            float pj0 = sPj[nt * 8 + 2 * tg];
            float pj1 = sPj[nt * 8 + 2 * tg + 1];
            s[nt][0] = c[0] * 0.125f + pi0 - pj0;
            s[nt][1] = c[1] * 0.125f + pi0 - pj1;
            s[nt][2] = c[2] * 0.125f + pi1 - pj0;
            s[nt][3] = c[3] * 0.125f + pi1 - pj1;
        }

        float t0 = -1e30f, t1 = -1e30f;
#pragma unroll
        for (int nt = 0; nt < 8; ++nt) {
            t0 = fmaxf(t0, fmaxf(s[nt][0], s[nt][1]));
            t1 = fmaxf(t1, fmaxf(s[nt][2], s[nt][3]));
        }
        t0 = fmaxf(t0, __shfl_xor_sync(0xffffffffu, t0, 1));
        t0 = fmaxf(t0, __shfl_xor_sync(0xffffffffu, t0, 2));
        t1 = fmaxf(t1, __shfl_xor_sync(0xffffffffu, t1, 1));
        t1 = fmaxf(t1, __shfl_xor_sync(0xffffffffu, t1, 2));

        float mn0 = fmaxf(m0, t0), mn1 = fmaxf(m1, t1);
        float cor0 = __expf(m0 - mn0), cor1 = __expf(m1 - mn1);
        l0 *= cor0; l1 *= cor1;
#pragma unroll
        for (int nt = 0; nt < 8; ++nt) {
            o[nt][0] *= cor0; o[nt][1] *= cor0;
            o[nt][2] *= cor1; o[nt][3] *= cor1;
        }

        float ls0 = 0.f, ls1 = 0.f;
#pragma unroll
        for (int nt = 0; nt < 8; ++nt) {
            float p00 = __expf(s[nt][0] - mn0);
            float p01 = __expf(s[nt][1] - mn0);
            float p10 = __expf(s[nt][2] - mn1);
            float p11 = __expf(s[nt][3] - mn1);
            ls0 += p00 + p01; ls1 += p10 + p11;
            *(float2*)&sQ[r0 * QSTR + nt * 8 + 2 * tg] = make_float2(p00, p01);
            *(float2*)&sQ[r1 * QSTR + nt * 8 + 2 * tg] = make_float2(p10, p11);
        }
        ls0 += __shfl_xor_sync(0xffffffffu, ls0, 1);
        ls0 += __shfl_xor_sync(0xffffffffu, ls0, 2);
        ls1 += __shfl_xor_sync(0xffffffffu, ls1, 1);
        ls1 += __shfl_xor_sync(0xffffffffu, ls1, 2);
        l0 += ls0; l1 += ls1;
        m0 = mn0; m1 = mn1;
        __syncwarp();

#pragma unroll
        for (int kc = 0; kc < 8; ++kc) {
            uint32_t a[4];
            a[0] = __float_as_uint(sQ[r0 * QSTR + kc * 8 + tg]);
            a[1] = __float_as_uint(sQ[r1 * QSTR + kc * 8 + tg]);
            a[2] = __float_as_uint(sQ[r0 * QSTR + kc * 8 + tg + 4]);
            a[3] = __float_as_uint(sQ[r1 * QSTR + kc * 8 + tg + 4]);
#pragma unroll
            for (int nt = 0; nt < 8; ++nt) {
                uint32_t b[2];
                b[0] = __float_as_uint(sV[(kc * 8 + tg) * VSTR + nt * 8 + g]);
                b[1] = __float_as_uint(sV[(kc * 8 + tg + 4) * VSTR + nt * 8 + g]);
                mma8(o[nt], a, b);
            }
        }
        __syncthreads();
    }

    const float inv0 = 1.f / l0, inv1 = 1.f / l1;
    const int b = bh / H_;
    const int h = bh % H_;
    const int qA = q0 + r0, qB = q0 + r1;
    float* oA = &out[((size_t)(b * N_ + qA)) * D_ + h * DH_];
    float* oB = &out[((size_t)(b * N_ + qB)) * D_ + h * DH_];
#pragma unroll
    for (int nt = 0; nt < 8; ++nt) {
        *(float2*)&oA[nt * 8 + 2 * tg] = make_float2(o[nt][0] * inv0, o[nt][1] * inv0);
        *(float2*)&oB[nt * 8 + 2 * tg] = make_float2(o[nt][2] * inv1, o[nt][3] * inv1);
    }
}

// ---------------------------------------------------------------------------
extern "C" void kernel_launch(void* const* d_in, const int* in_sizes, int n_in,
                              void* d_out, int out_size)
{
    const float* x     = (const float*)d_in[0];
    const float* coords= (const float*)d_in[1];
    const float* Wqkv  = (const float*)d_in[2];
    const float* bqkv  = (const float*)d_in[3];
    const float* relw  = (const float*)d_in[4];
    float* out = (float*)d_out;

    (void)in_sizes; (void)n_in; (void)out_size;

    static bool attr_set = false;
    if (!attr_set) {
        cudaFuncSetAttribute(attn_mma_kernel,
                             cudaFuncAttributeMaxDynamicSharedMemorySize,
                             ATTN_SMEM);
        attr_set = true;
    }

    proj_kernel<<<(BH_ * N_ + 255) / 256, 256>>>(coords, relw);

    dim3 ggrid(N3_ / 128, M_ / 128);   // (18, 32)
    qkv_gemm_bf16_kernel<<<ggrid, 256>>>(x, Wqkv, bqkv);

    dim3 agrid(N_ / 64, BH_);          // (16, 48)
    attn_mma_kernel<<<agrid, 128, ATTN_SMEM>>>(out);
}

// round 4
// speedup vs baseline: 4.1658x; 1.2191x over previous
#include <cuda_runtime.h>
#include <cuda_bf16.h>
#include <cstdint>

// Problem constants
#define B_  4
#define N_  1024
#define D_  768
#define H_  12
#define DH_ 64
#define BH_ (B_ * H_)      // 48
#define M_  (B_ * N_)      // 4096 rows of x
#define N3_ (3 * D_)       // 2304 output cols of qkv

// Scratch: q,k,v in (B,H,N,Dh) layout + proj (B,H,N)
__device__ float g_q[BH_ * N_ * DH_];
__device__ float g_k[BH_ * N_ * DH_];
__device__ float g_v[BH_ * N_ * DH_];
__device__ float g_proj[BH_ * N_];

// ---------------------------------------------------------------------------
// bf16 m16n8k16 mma (row.col, fp32 accumulate)
// ---------------------------------------------------------------------------
__device__ __forceinline__ void mma16816(float c[4], const uint32_t a[4],
                                         const uint32_t b[2]) {
    asm volatile(
        "mma.sync.aligned.m16n8k16.row.col.f32.bf16.bf16.f32 "
        "{%0,%1,%2,%3}, {%4,%5,%6,%7}, {%8,%9}, {%0,%1,%2,%3};"
        : "+f"(c[0]), "+f"(c[1]), "+f"(c[2]), "+f"(c[3])
        : "r"(a[0]), "r"(a[1]), "r"(a[2]), "r"(a[3]), "r"(b[0]), "r"(b[1]));
}

// split two floats into packed bf16x2 hi and lo parts
__device__ __forceinline__ void split2(float a, float b,
                                       uint32_t& hi, uint32_t& lo) {
    __nv_bfloat16 ha = __float2bfloat16(a);
    __nv_bfloat16 hb = __float2bfloat16(b);
    __nv_bfloat162 h; h.x = ha; h.y = hb;
    hi = *(const uint32_t*)&h;
    __nv_bfloat162 l;
    l.x = __float2bfloat16(a - __bfloat162float(ha));
    l.y = __float2bfloat16(b - __bfloat162float(hb));
    lo = *(const uint32_t*)&l;
}

// ---------------------------------------------------------------------------
// Kernel 1: qkv = x @ Wqkv^T + bqkv via bf16 tensor cores (3-term hi/lo split)
// ---------------------------------------------------------------------------
#define ASTR 40

__global__ __launch_bounds__(256) void qkv_gemm_bf16_kernel(
    const float* __restrict__ x, const float* __restrict__ W,
    const float* __restrict__ bias)
{
    __shared__ __nv_bfloat16 Ah[128][ASTR];
    __shared__ __nv_bfloat16 Al[128][ASTR];
    __shared__ __nv_bfloat16 Bh[128][ASTR];
    __shared__ __nv_bfloat16 Bl[128][ASTR];

    const int tid  = threadIdx.x;
    const int warp = tid >> 5;
    const int lane = tid & 31;
    const int wm = warp >> 2;
    const int wn = warp & 3;
    const int g  = lane >> 2;
    const int tg = lane & 3;
    const int m0 = blockIdx.y * 128;
    const int n0 = blockIdx.x * 128;

    float acc[4][4][4];
#pragma unroll
    for (int mt = 0; mt < 4; ++mt)
#pragma unroll
        for (int nt = 0; nt < 4; ++nt)
#pragma unroll
            for (int j = 0; j < 4; ++j) acc[mt][nt][j] = 0.f;

    for (int k0 = 0; k0 < D_; k0 += 32) {
#pragma unroll
        for (int it = 0; it < 4; ++it) {
            int idx = it * 256 + tid;
            int r   = idx >> 3;
            int c4  = (idx & 7) * 4;
            float4 a = *(const float4*)&x[(size_t)(m0 + r) * D_ + k0 + c4];
            uint32_t h01, l01, h23, l23;
            split2(a.x, a.y, h01, l01);
            split2(a.z, a.w, h23, l23);
            *(uint32_t*)&Ah[r][c4]     = h01;
            *(uint32_t*)&Ah[r][c4 + 2] = h23;
            *(uint32_t*)&Al[r][c4]     = l01;
            *(uint32_t*)&Al[r][c4 + 2] = l23;

            float4 b = *(const float4*)&W[(size_t)(n0 + r) * D_ + k0 + c4];
            split2(b.x, b.y, h01, l01);
            split2(b.z, b.w, h23, l23);
            *(uint32_t*)&Bh[r][c4]     = h01;
            *(uint32_t*)&Bh[r][c4 + 2] = h23;
            *(uint32_t*)&Bl[r][c4]     = l01;
            *(uint32_t*)&Bl[r][c4 + 2] = l23;
        }
        __syncthreads();

#pragma unroll
        for (int ks = 0; ks < 2; ++ks) {
            const int kb = ks * 16 + 2 * tg;
            uint32_t ahi[4][4], alo[4][4];
#pragma unroll
            for (int mt = 0; mt < 4; ++mt) {
                int r0 = wm * 64 + mt * 16 + g;
                int r1 = r0 + 8;
                ahi[mt][0] = *(const uint32_t*)&Ah[r0][kb];
                ahi[mt][1] = *(const uint32_t*)&Ah[r1][kb];
                ahi[mt][2] = *(const uint32_t*)&Ah[r0][kb + 8];
                ahi[mt][3] = *(const uint32_t*)&Ah[r1][kb + 8];
                alo[mt][0] = *(const uint32_t*)&Al[r0][kb];
                alo[mt][1] = *(const uint32_t*)&Al[r1][kb];
                alo[mt][2] = *(const uint32_t*)&Al[r0][kb + 8];
                alo[mt][3] = *(const uint32_t*)&Al[r1][kb + 8];
            }
            uint32_t bhi[4][2], blo[4][2];
#pragma unroll
            for (int nt = 0; nt < 4; ++nt) {
                int n = wn * 32 + nt * 8 + g;
                bhi[nt][0] = *(const uint32_t*)&Bh[n][kb];
                bhi[nt][1] = *(const uint32_t*)&Bh[n][kb + 8];
                blo[nt][0] = *(const uint32_t*)&Bl[n][kb];
                blo[nt][1] = *(const uint32_t*)&Bl[n][kb + 8];
            }
#pragma unroll
            for (int mt = 0; mt < 4; ++mt)
#pragma unroll
                for (int nt = 0; nt < 4; ++nt) {
                    mma16816(acc[mt][nt], ahi[mt], bhi[nt]);
                    mma16816(acc[mt][nt], ahi[mt], blo[nt]);
                    mma16816(acc[mt][nt], alo[mt], bhi[nt]);
                }
        }
        __syncthreads();
    }

    const int which = n0 / D_;
    float* dst = (which == 0) ? g_q : (which == 1) ? g_k : g_v;
    const int colbase = n0 % D_;

#pragma unroll
    for (int nt = 0; nt < 4; ++nt) {
        const int cloc = wn * 32 + nt * 8 + 2 * tg;
        const int col  = colbase + cloc;
        const int h    = col >> 6;
        const int d    = col & 63;
        float2 bv = *(const float2*)&bias[n0 + cloc];
#pragma unroll
        for (int mt = 0; mt < 4; ++mt) {
            int rA = m0 + wm * 64 + mt * 16 + g;
            int rB = rA + 8;
            int bb = rA >> 10;
            float* rowA = &dst[((size_t)(bb * H_ + h) * N_ + (rA & 1023)) * DH_ + d];
            float* rowB = &dst[((size_t)(bb * H_ + h) * N_ + (rB & 1023)) * DH_ + d];
            *(float2*)rowA = make_float2(acc[mt][nt][0] + bv.x,
                                         acc[mt][nt][1] + bv.y);
            *(float2*)rowB = make_float2(acc[mt][nt][2] + bv.x,
                                         acc[mt][nt][3] + bv.y);
        }
    }
}

// ---------------------------------------------------------------------------
// Kernel 2: proj[b,h,n] = sum_c coords[b,n,c] * rel_weight[h,c]
// ---------------------------------------------------------------------------
__global__ void proj_kernel(const float* __restrict__ coords,
                            const float* __restrict__ relw)
{
    int idx = blockIdx.x * blockDim.x + threadIdx.x;
    if (idx >= BH_ * N_) return;
    int n = idx & 1023;
    int h = (idx >> 10) % H_;
    int b = idx / (H_ * N_);
    const float* c = &coords[(size_t)(b * N_ + n) * 3];
    const float* w = &relw[h * 3];
    g_proj[idx] = c[0] * w[0] + c[1] * w[1] + c[2] * w[2];
}

// ---------------------------------------------------------------------------
// Kernel 3: tensor-core flash attention.
// QK^T: bf16 m16n8k16 3-term split (96 mma/warp-tile, fp32-grade scores).
// PV:   tf32 m16n8k8 single-pass (accuracy-critical term, unchanged).
// ---------------------------------------------------------------------------
#define QSTR 68   // fp32 stride: sQ / P
#define KSTR 72   // bf16-half stride: sKh / sKl  (word stride 36 -> conflict-free)
#define VSTR 72   // fp32 stride: sV
#define ATTN_SMEM (64 * QSTR * 4 + 2 * 64 * KSTR * 2 + 64 * VSTR * 4 + 64 * 4)

__device__ __forceinline__ void mma8(float c[4], const uint32_t a[4],
                                     const uint32_t b[2]) {
    asm volatile(
        "mma.sync.aligned.m16n8k8.row.col.f32.tf32.tf32.f32 "
        "{%0,%1,%2,%3}, {%4,%5,%6,%7}, {%8,%9}, {%0,%1,%2,%3};"
        : "+f"(c[0]), "+f"(c[1]), "+f"(c[2]), "+f"(c[3])
        : "r"(a[0]), "r"(a[1]), "r"(a[2]), "r"(a[3]), "r"(b[0]), "r"(b[1]));
}

__global__ __launch_bounds__(128) void attn_mma_kernel(float* __restrict__ out)
{
    extern __shared__ char smraw[];
    float*         sQ  = (float*)smraw;                       // 64 x QSTR (reused as P)
    __nv_bfloat16* sKh = (__nv_bfloat16*)(sQ + 64 * QSTR);    // 64 x KSTR
    __nv_bfloat16* sKl = sKh + 64 * KSTR;                     // 64 x KSTR
    float*         sV  = (float*)(sKl + 64 * KSTR);           // 64 x VSTR
    float*         sPj = sV + 64 * VSTR;                      // 64

    const int bh = blockIdx.y;
    const int q0 = blockIdx.x * 64;
    const int tid = threadIdx.x;
    const int w = tid >> 5;
    const int lane = tid & 31;
    const int g = lane >> 2;
    const int tg = lane & 3;
    const int r0 = w * 16 + g;
    const int r1 = r0 + 8;

    // ---- load Q tile ----
#pragma unroll
    for (int t = 0; t < 8; ++t) {
        int idx = t * 128 + tid;
        int r = idx >> 4;
        int c4 = (idx & 15) << 2;
        *(float4*)&sQ[r * QSTR + c4] =
            *(const float4*)&g_q[((size_t)bh * N_ + q0 + r) * DH_ + c4];
    }
    __syncthreads();

    // ---- build bf16 hi/lo A fragments for QK^T (4 k16-chunks) ----
    uint32_t qhi[4][4], qlo[4][4];
#pragma unroll
    for (int kc = 0; kc < 4; ++kc) {
        const int kb = kc * 16 + 2 * tg;
        split2(sQ[r0 * QSTR + kb],     sQ[r0 * QSTR + kb + 1], qhi[kc][0], qlo[kc][0]);
        split2(sQ[r1 * QSTR + kb],     sQ[r1 * QSTR + kb + 1], qhi[kc][1], qlo[kc][1]);
        split2(sQ[r0 * QSTR + kb + 8], sQ[r0 * QSTR + kb + 9], qhi[kc][2], qlo[kc][2]);
        split2(sQ[r1 * QSTR + kb + 8], sQ[r1 * QSTR + kb + 9], qhi[kc][3], qlo[kc][3]);
    }
    __syncthreads();    // sQ may now be reused as P

    const float pi0 = g_proj[bh * N_ + q0 + r0];
    const float pi1 = g_proj[bh * N_ + q0 + r1];

    float o[8][4];
#pragma unroll
    for (int nt = 0; nt < 8; ++nt)
#pragma unroll
        for (int j = 0; j < 4; ++j) o[nt][j] = 0.f;
    float m0 = -1e30f, m1 = -1e30f, l0 = 0.f, l1 = 0.f;

    for (int kt = 0; kt < N_ / 64; ++kt) {
        // ---- cooperative load: K -> bf16 hi/lo, V -> fp32 ----
        const size_t kbase = ((size_t)bh * N_ + kt * 64) * DH_;
#pragma unroll
        for (int t = 0; t < 8; ++t) {
            int idx = t * 128 + tid;
            int r = idx >> 4;
            int c4 = (idx & 15) << 2;
            float4 kf = *(const float4*)&g_k[kbase + r * DH_ + c4];
            uint32_t h01, l01, h23, l23;
            split2(kf.x, kf.y, h01, l01);
            split2(kf.z, kf.w, h23, l23);
            *(uint32_t*)&sKh[r * KSTR + c4]     = h01;
            *(uint32_t*)&sKh[r * KSTR + c4 + 2] = h23;
            *(uint32_t*)&sKl[r * KSTR + c4]     = l01;
            *(uint32_t*)&sKl[r * KSTR + c4 + 2] = l23;
            *(float4*)&sV[r * VSTR + c4] =
                *(const float4*)&g_v[kbase + r * DH_ + c4];
        }
        if (tid < 64) sPj[tid] = g_proj[bh * N_ + kt * 64 + tid];
        __syncthreads();

        // ---- S = Q K^T (bf16 3-term) ----
        float s[8][4];
#pragma unroll
        for (int nt = 0; nt < 8; ++nt) {
            float c[4] = {0.f, 0.f, 0.f, 0.f};
            const int key = nt * 8 + g;
#pragma unroll
            for (int kc = 0; kc < 4; ++kc) {
                const int kb = kc * 16 + 2 * tg;
                uint32_t bhf[2], blf[2];
                bhf[0] = *(const uint32_t*)&sKh[key * KSTR + kb];
                bhf[1] = *(const uint32_t*)&sKh[key * KSTR + kb + 8];
                blf[0] = *(const uint32_t*)&sKl[key * KSTR + kb];
                blf[1] = *(const uint32_t*)&sKl[key * KSTR + kb + 8];
                mma16816(c, qhi[kc], bhf);
                mma16816(c, qhi[kc], blf);
                mma16816(c, qlo[kc], bhf);
            }
            float pj0 = sPj[nt * 8 + 2 * tg];
            float pj1 = sPj[nt * 8 + 2 * tg + 1];
            s[nt][0] = c[0] * 0.125f + pi0 - pj0;
            s[nt][1] = c[1] * 0.125f + pi0 - pj1;
            s[nt][2] = c[2] * 0.125f + pi1 - pj0;
            s[nt][3] = c[3] * 0.125f + pi1 - pj1;
        }

        // ---- online softmax ----
        float t0 = -1e30f, t1 = -1e30f;
#pragma unroll
        for (int nt = 0; nt < 8; ++nt) {
            t0 = fmaxf(t0, fmaxf(s[nt][0], s[nt][1]));
            t1 = fmaxf(t1, fmaxf(s[nt][2], s[nt][3]));
        }
        t0 = fmaxf(t0, __shfl_xor_sync(0xffffffffu, t0, 1));
        t0 = fmaxf(t0, __shfl_xor_sync(0xffffffffu, t0, 2));
        t1 = fmaxf(t1, __shfl_xor_sync(0xffffffffu, t1, 1));
        t1 = fmaxf(t1, __shfl_xor_sync(0xffffffffu, t1, 2));

        float mn0 = fmaxf(m0, t0), mn1 = fmaxf(m1, t1);
        float cor0 = __expf(m0 - mn0), cor1 = __expf(m1 - mn1);
        l0 *= cor0; l1 *= cor1;
#pragma unroll
        for (int nt = 0; nt < 8; ++nt) {
            o[nt][0] *= cor0; o[nt][1] *= cor0;
            o[nt][2] *= cor1; o[nt][3] *= cor1;
        }

        float ls0 = 0.f, ls1 = 0.f;
#pragma unroll
        for (int nt = 0; nt < 8; ++nt) {
            float p00 = __expf(s[nt][0] - mn0);
            float p01 = __expf(s[nt][1] - mn0);
            float p10 = __expf(s[nt][2] - mn1);
            float p11 = __expf(s[nt][3] - mn1);
            ls0 += p00 + p01; ls1 += p10 + p11;
            *(float2*)&sQ[r0 * QSTR + nt * 8 + 2 * tg] = make_float2(p00, p01);
            *(float2*)&sQ[r1 * QSTR + nt * 8 + 2 * tg] = make_float2(p10, p11);
        }
        ls0 += __shfl_xor_sync(0xffffffffu, ls0, 1);
        ls0 += __shfl_xor_sync(0xffffffffu, ls0, 2);
        ls1 += __shfl_xor_sync(0xffffffffu, ls1, 1);
        ls1 += __shfl_xor_sync(0xffffffffu, ls1, 2);
        l0 += ls0; l1 += ls1;
        m0 = mn0; m1 = mn1;
        __syncwarp();

        // ---- O += P V (tf32) ----
#pragma unroll
        for (int kc = 0; kc < 8; ++kc) {
            uint32_t a[4];
            a[0] = __float_as_uint(sQ[r0 * QSTR + kc * 8 + tg]);
            a[1] = __float_as_uint(sQ[r1 * QSTR + kc * 8 + tg]);
            a[2] = __float_as_uint(sQ[r0 * QSTR + kc * 8 + tg + 4]);
            a[3] = __float_as_uint(sQ[r1 * QSTR + kc * 8 + tg + 4]);
#pragma unroll
            for (int nt = 0; nt < 8; ++nt) {
                uint32_t b[2];
                b[0] = __float_as_uint(sV[(kc * 8 + tg) * VSTR + nt * 8 + g]);
                b[1] = __float_as_uint(sV[(kc * 8 + tg + 4) * VSTR + nt * 8 + g]);
                mma8(o[nt], a, b);
            }
        }
        __syncthreads();
    }

    // ---- epilogue ----
    const float inv0 = 1.f / l0, inv1 = 1.f / l1;
    const int b = bh / H_;
    const int h = bh % H_;
    const int qA = q0 + r0, qB = q0 + r1;
    float* oA = &out[((size_t)(b * N_ + qA)) * D_ + h * DH_];
    float* oB = &out[((size_t)(b * N_ + qB)) * D_ + h * DH_];
#pragma unroll
    for (int nt = 0; nt < 8; ++nt) {
        *(float2*)&oA[nt * 8 + 2 * tg] = make_float2(o[nt][0] * inv0, o[nt][1] * inv0);
        *(float2*)&oB[nt * 8 + 2 * tg] = make_float2(o[nt][2] * inv1, o[nt][3] * inv1);
    }
}

// ---------------------------------------------------------------------------
extern "C" void kernel_launch(void* const* d_in, const int* in_sizes, int n_in,
                              void* d_out, int out_size)
{
    const float* x     = (const float*)d_in[0];
    const float* coords= (const float*)d_in[1];
    const float* Wqkv  = (const float*)d_in[2];
    const float* bqkv  = (const float*)d_in[3];
    const float* relw  = (const float*)d_in[4];
    float* out = (float*)d_out;

    (void)in_sizes; (void)n_in; (void)out_size;

    static bool attr_set = false;
    if (!attr_set) {
        cudaFuncSetAttribute(attn_mma_kernel,
                             cudaFuncAttributeMaxDynamicSharedMemorySize,
                             ATTN_SMEM);
        attr_set = true;
    }

    proj_kernel<<<(BH_ * N_ + 255) / 256, 256>>>(coords, relw);

    dim3 ggrid(N3_ / 128, M_ / 128);   // (18, 32)
    qkv_gemm_bf16_kernel<<<ggrid, 256>>>(x, Wqkv, bqkv);

    dim3 agrid(N_ / 64, BH_);          // (16, 48)
    attn_mma_kernel<<<agrid, 128, ATTN_SMEM>>>(out);
}